// round 7
// baseline (speedup 1.0000x reference)
#include <cuda_runtime.h>

// Problem constants
#define B_ 4
#define T_ 1024
#define C_ 1024
#define H_ 16
#define L_ 256
#define D_ 64
#define M_ (B_*T_)   // 4096 rows

// ---------------------------------------------------------------------------
// Scratch (device globals: no allocation allowed in kernel_launch)
// ---------------------------------------------------------------------------
__device__ float g_kv_down[M_ * L_];            //  4 MB
__device__ float g_q_down [M_ * L_];            //  4 MB
__device__ float g_k      [M_ * C_];            // 16 MB  (B,T,C) row-major
__device__ float g_q      [M_ * C_];            // 16 MB
__device__ float g_v      [M_ * C_];            // 16 MB
__device__ float g_ctx    [M_ * C_];            // 16 MB
__device__ float g_interT [67108864];           // 256 MB: (B,H,Tq,Tk)

// ---------------------------------------------------------------------------
// Generic fp32 GEMM: C[M,N] = A[M,K] @ B[K,N] (+bias). 128x128 tile, BK=8,
// 256 threads, 8x8 per-thread micro-tile, float4 smem fragments.
// Requires M%128==0, N%128==0, K%8==0 (true for all call sites here).
// ---------------------------------------------------------------------------
__global__ __launch_bounds__(256)
void sgemm128(const float* __restrict__ A, const float* __restrict__ Bm,
              float* __restrict__ Cm, int Mdim, int Ndim, int Kdim,
              const float* __restrict__ bias)
{
    __shared__ float As[8][128];
    __shared__ float Bs[8][128];

    const int tid = threadIdx.x;
    const int tx = tid & 15;        // 0..15  -> N direction
    const int ty = tid >> 4;        // 0..15  -> M direction
    const int m0 = blockIdx.y * 128;
    const int n0 = blockIdx.x * 128;

    // A-tile load mapping: 128 rows x 8 cols = 256 float4
    const int arow = tid >> 1;            // 0..127
    const int akb  = (tid & 1) * 4;       // 0 or 4
    // B-tile load mapping: 8 rows x 128 cols = 256 float4
    const int brow = tid >> 5;            // 0..7
    const int bnb  = (tid & 31) * 4;      // 0..124

    float acc[8][8];
#pragma unroll
    for (int i = 0; i < 8; i++)
#pragma unroll
        for (int j = 0; j < 8; j++) acc[i][j] = 0.f;

    for (int k0 = 0; k0 < Kdim; k0 += 8) {
        float4 a = *(const float4*)&A[(size_t)(m0 + arow) * Kdim + k0 + akb];
        As[akb + 0][arow] = a.x;
        As[akb + 1][arow] = a.y;
        As[akb + 2][arow] = a.z;
        As[akb + 3][arow] = a.w;
        *(float4*)&Bs[brow][bnb] =
            *(const float4*)&Bm[(size_t)(k0 + brow) * Ndim + n0 + bnb];
        __syncthreads();

#pragma unroll
        for (int kk = 0; kk < 8; kk++) {
            float ar[8], br[8];
            *(float4*)&ar[0] = *(float4*)&As[kk][ty * 8];
            *(float4*)&ar[4] = *(float4*)&As[kk][ty * 8 + 4];
            *(float4*)&br[0] = *(float4*)&Bs[kk][tx * 8];
            *(float4*)&br[4] = *(float4*)&Bs[kk][tx * 8 + 4];
#pragma unroll
            for (int i = 0; i < 8; i++)
#pragma unroll
                for (int j = 0; j < 8; j++) acc[i][j] += ar[i] * br[j];
        }
        __syncthreads();
    }

    float bi[8];
#pragma unroll
    for (int j = 0; j < 8; j++) bi[j] = bias ? bias[n0 + tx * 8 + j] : 0.f;

#pragma unroll
    for (int i = 0; i < 8; i++) {
        size_t off = (size_t)(m0 + ty * 8 + i) * Ndim + n0 + tx * 8;
        float4 o0 = make_float4(acc[i][0] + bi[0], acc[i][1] + bi[1],
                                acc[i][2] + bi[2], acc[i][3] + bi[3]);
        float4 o1 = make_float4(acc[i][4] + bi[4], acc[i][5] + bi[5],
                                acc[i][6] + bi[6], acc[i][7] + bi[7]);
        *(float4*)&Cm[off]     = o0;
        *(float4*)&Cm[off + 4] = o1;
    }
}

// ---------------------------------------------------------------------------
// interaction_matrix transpose: (B, Tk, Tq, H) -> (B, H, Tq, Tk).
// Tile = (k:16, q:16, h:16). Source reads are 256-float contiguous runs
// (q*H+h contiguous); dest writes are 16-float (64B) aligned runs in k.
// ---------------------------------------------------------------------------
__global__ __launch_bounds__(256)
void transpose_inter(const float* __restrict__ src, float* __restrict__ dst)
{
    __shared__ float s[16][256];
    const int t  = threadIdx.x;
    const int k0 = blockIdx.x * 16;
    const int q0 = blockIdx.y * 16;
    const int b  = blockIdx.z;

    const float* sp = src + (size_t)b * T_ * T_ * H_ + (size_t)q0 * H_;
#pragma unroll
    for (int kk = 0; kk < 16; kk++)
        s[kk][t] = sp[(size_t)(k0 + kk) * T_ * H_ + t];
    __syncthreads();

    const int q = t >> 4;
    const int h = t & 15;
    float* dp = dst + ((size_t)(b * H_ + h) * T_ + q0 + q) * T_ + k0;
#pragma unroll
    for (int kk4 = 0; kk4 < 4; kk4++) {
        float4 v = make_float4(s[kk4 * 4 + 0][t], s[kk4 * 4 + 1][t],
                               s[kk4 * 4 + 2][t], s[kk4 * 4 + 3][t]);
        *(float4*)&dp[kk4 * 4] = v;
    }
}

// ---------------------------------------------------------------------------
// Flash attention with interaction bias + padding + causal masks.
// Block: 256 threads = 64 q-rows x 4 lanes/row (lanes of a row adjacent in a
// warp -> shfl row reductions). Br=64, Bc=32, D=64. One block per (qtile,h,b).
//   score[q,k] = 0.125*dot(q,k)    -> pad(q)==0 ? -1e9 : .
//                -> k>q ? -inf : . -> + interT[b,h,q,k]
// Online softmax; ctx written in (B,T,C) layout for the output GEMM.
// smem strides chosen for conflict-free float4 access:
//   q_s stride 68 (r in lane/4 -> distinct bank groups)
//   k_s/v_s stride 68 with interleaved column map c = c4 + 4j and
//   d map d = 4*c4 + 16*i (lane groups hit bank groups {0,4,8,12})
//   p_s stride 36
// ---------------------------------------------------------------------------
__global__ __launch_bounds__(256)
void attn_kernel(const float* __restrict__ Q, const float* __restrict__ K,
                 const float* __restrict__ V, const int* __restrict__ pad,
                 const float* __restrict__ interT, float* __restrict__ ctx)
{
    __shared__ float q_s[64 * 68];
    __shared__ float k_s[32 * 68];
    __shared__ float v_s[32 * 68];
    __shared__ float p_s[64 * 36];   // holds interaction tile, then P tile

    const float NEG_INF = __int_as_float(0xff800000);

    const int tid = threadIdx.x;
    const int r   = tid >> 2;        // q-row within tile (0..63)
    const int c4  = tid & 3;         // lane within row (0..3)
    const int q0  = blockIdx.x * 64;
    const int h   = blockIdx.y;
    const int b   = blockIdx.z;

    const float* qp = Q + (size_t)(b * T_) * C_ + h * D_;
    const float* kp = K + (size_t)(b * T_) * C_ + h * D_;
    const float* vp = V + (size_t)(b * T_) * C_ + h * D_;
    const float* ip = interT + ((size_t)(b * H_ + h) * T_) * T_;

    // Load Q tile (64 x 64): 1024 float4
#pragma unroll
    for (int it = 0; it < 4; it++) {
        int idx = tid + it * 256;
        int row = idx >> 4, d4 = (idx & 15) * 4;
        *(float4*)&q_s[row * 68 + d4] =
            *(const float4*)&qp[(size_t)(q0 + row) * C_ + d4];
    }

    const int myq = q0 + r;
    const int pd  = pad[b * T_ + myq];

    float m = NEG_INF, l = 0.f;
    float4 acc0 = {0,0,0,0}, acc1 = {0,0,0,0}, acc2 = {0,0,0,0}, acc3 = {0,0,0,0};

    for (int k0 = 0; k0 < q0 + 64; k0 += 32) {
        // Cooperative loads: K tile, V tile (32x64), interaction tile (64x32)
#pragma unroll
        for (int it = 0; it < 2; it++) {
            int idx = tid + it * 256;
            int row = idx >> 4, d4 = (idx & 15) * 4;
            *(float4*)&k_s[row * 68 + d4] =
                *(const float4*)&kp[(size_t)(k0 + row) * C_ + d4];
            *(float4*)&v_s[row * 68 + d4] =
                *(const float4*)&vp[(size_t)(k0 + row) * C_ + d4];
            int irow = idx >> 3, ic = (idx & 7) * 4;
            *(float4*)&p_s[irow * 36 + ic] =
                *(const float4*)&ip[(size_t)(q0 + irow) * T_ + k0 + ic];
        }
        __syncthreads();

        // S = 0.125 * Q K^T  (8 columns per thread, c = c4 + 4j)
        float s[8];
#pragma unroll
        for (int j = 0; j < 8; j++) s[j] = 0.f;
#pragma unroll
        for (int d = 0; d < 64; d += 4) {
            float4 qv = *(float4*)&q_s[r * 68 + d];
#pragma unroll
            for (int j = 0; j < 8; j++) {
                int c = c4 + 4 * j;
                float4 kv = *(float4*)&k_s[c * 68 + d];
                s[j] += qv.x * kv.x + qv.y * kv.y + qv.z * kv.z + qv.w * kv.w;
            }
        }

        // masks + interaction bias, tile row-max
        float mt = NEG_INF;
#pragma unroll
        for (int j = 0; j < 8; j++) {
            int c = c4 + 4 * j;
            float sv = s[j] * 0.125f;
            if (pd == 0)          sv = -1e9f;
            if (k0 + c > myq)     sv = NEG_INF;
            sv += p_s[r * 36 + c];           // interaction (finite; -inf stays)
            s[j] = sv;
            mt = fmaxf(mt, sv);
        }
        mt = fmaxf(mt, __shfl_xor_sync(0xffffffffu, mt, 1));
        mt = fmaxf(mt, __shfl_xor_sync(0xffffffffu, mt, 2));

        float mnew = fmaxf(m, mt);
        float f = (m == NEG_INF) ? 0.f : __expf(m - mnew);

        float lt = 0.f;
#pragma unroll
        for (int j = 0; j < 8; j++) {
            float p = (s[j] == NEG_INF) ? 0.f : __expf(s[j] - mnew);
            s[j] = p;
            lt += p;
        }
        lt += __shfl_xor_sync(0xffffffffu, lt, 1);
        lt += __shfl_xor_sync(0xffffffffu, lt, 2);
        l = l * f + lt;
        m = mnew;

        acc0.x *= f; acc0.y *= f; acc0.z *= f; acc0.w *= f;
        acc1.x *= f; acc1.y *= f; acc1.z *= f; acc1.w *= f;
        acc2.x *= f; acc2.y *= f; acc2.z *= f; acc2.w *= f;
        acc3.x *= f; acc3.y *= f; acc3.z *= f; acc3.w *= f;

        // publish P tile (each thread writes exactly the slots it read)
#pragma unroll
        for (int j = 0; j < 8; j++) p_s[r * 36 + c4 + 4 * j] = s[j];
        __syncthreads();

        // ctx += P V : thread owns d = 4*c4 + 16*i (+0..3), i = 0..3
        const int dof = c4 * 4;
#pragma unroll 8
        for (int c = 0; c < 32; c++) {
            float pv = p_s[r * 36 + c];
            float4 v0 = *(float4*)&v_s[c * 68 + dof];
            float4 v1 = *(float4*)&v_s[c * 68 + 16 + dof];
            float4 v2 = *(float4*)&v_s[c * 68 + 32 + dof];
            float4 v3 = *(float4*)&v_s[c * 68 + 48 + dof];
            acc0.x += pv * v0.x; acc0.y += pv * v0.y; acc0.z += pv * v0.z; acc0.w += pv * v0.w;
            acc1.x += pv * v1.x; acc1.y += pv * v1.y; acc1.z += pv * v1.z; acc1.w += pv * v1.w;
            acc2.x += pv * v2.x; acc2.y += pv * v2.y; acc2.z += pv * v2.z; acc2.w += pv * v2.w;
            acc3.x += pv * v3.x; acc3.y += pv * v3.y; acc3.z += pv * v3.z; acc3.w += pv * v3.w;
        }
        __syncthreads();   // protect k_s/v_s/p_s before next tile's loads
    }

    // epilogue: normalize and write ctx in (B,T,C) layout
    const float inv = 1.f / l;
    float* op = ctx + (size_t)(b * T_ + myq) * C_ + h * D_ + c4 * 4;
    float4 o;
    o = make_float4(acc0.x * inv, acc0.y * inv, acc0.z * inv, acc0.w * inv); *(float4*)&op[0]  = o;
    o = make_float4(acc1.x * inv, acc1.y * inv, acc1.z * inv, acc1.w * inv); *(float4*)&op[16] = o;
    o = make_float4(acc2.x * inv, acc2.y * inv, acc2.z * inv, acc2.w * inv); *(float4*)&op[32] = o;
    o = make_float4(acc3.x * inv, acc3.y * inv, acc3.z * inv, acc3.w * inv); *(float4*)&op[48] = o;
}

// ---------------------------------------------------------------------------
// Launch: 5 projection GEMMs, interaction transpose, attention, output GEMM.
// Default stream -> sequential dependencies, fully graph-capturable.
// ---------------------------------------------------------------------------
extern "C" void kernel_launch(void* const* d_in, const int* in_sizes, int n_in,
                              void* d_out, int out_size)
{
    const float* x       = (const float*)d_in[0];
    const int*   padding = (const int*)  d_in[1];
    const float* inter   = (const float*)d_in[2];
    const float* W_ckv   = (const float*)d_in[3];
    const float* W_cq    = (const float*)d_in[4];
    const float* W_kc    = (const float*)d_in[5];
    const float* W_qc    = (const float*)d_in[6];
    const float* W_vc    = (const float*)d_in[7];
    const float* W_proj  = (const float*)d_in[8];
    const float* b_proj  = (const float*)d_in[9];
    float* out = (float*)d_out;

    float *kv_down, *q_down, *kb, *qb, *vb, *ctx, *interT;
    cudaGetSymbolAddress((void**)&kv_down, g_kv_down);
    cudaGetSymbolAddress((void**)&q_down,  g_q_down);
    cudaGetSymbolAddress((void**)&kb,      g_k);
    cudaGetSymbolAddress((void**)&qb,      g_q);
    cudaGetSymbolAddress((void**)&vb,      g_v);
    cudaGetSymbolAddress((void**)&ctx,     g_ctx);
    cudaGetSymbolAddress((void**)&interT,  g_interT);

    dim3 blk(256);

    // down projections: (4096x1024)@(1024x256)
    sgemm128<<<dim3(L_ / 128, M_ / 128), blk>>>(x, W_ckv, kv_down, M_, L_, C_, nullptr);
    sgemm128<<<dim3(L_ / 128, M_ / 128), blk>>>(x, W_cq,  q_down,  M_, L_, C_, nullptr);

    // up projections: (4096x256)@(256x1024), (B,T,C) layout == (B,T,H,D)
    sgemm128<<<dim3(C_ / 128, M_ / 128), blk>>>(kv_down, W_kc, kb, M_, C_, L_, nullptr);
    sgemm128<<<dim3(C_ / 128, M_ / 128), blk>>>(q_down,  W_qc, qb, M_, C_, L_, nullptr);
    sgemm128<<<dim3(C_ / 128, M_ / 128), blk>>>(kv_down, W_vc, vb, M_, C_, L_, nullptr);

    // interaction matrix (B,Tk,Tq,H) -> (B,H,Tq,Tk)
    transpose_inter<<<dim3(T_ / 16, T_ / 16, B_), blk>>>(inter, interT);

    // attention -> ctx (B,T,C)
    attn_kernel<<<dim3(T_ / 64, H_, B_), blk>>>(qb, kb, vb, padding, interT, ctx);

    // output projection: (4096x1024)@(1024x1024) + bias
    sgemm128<<<dim3(C_ / 128, M_ / 128), blk>>>(ctx, W_proj, out, M_, C_, C_, b_proj);
}

// round 8
// speedup vs baseline: 1.3104x; 1.3104x over previous
#include <cuda_runtime.h>
#include <cuda_bf16.h>

// Problem constants
#define B_ 4
#define T_ 1024
#define C_ 1024
#define H_ 16
#define L_ 256
#define D_ 64
#define M_ (B_*T_)   // 4096 rows

// ---------------------------------------------------------------------------
// Scratch (device globals: no allocation allowed in kernel_launch)
// ---------------------------------------------------------------------------
__device__ float g_kv_down[M_ * L_];            //  4 MB
__device__ float g_q_down [M_ * L_];            //  4 MB
__device__ float g_k      [M_ * C_];            // 16 MB  (B,T,C) row-major
__device__ float g_q      [M_ * C_];            // 16 MB
__device__ float g_v      [M_ * C_];            // 16 MB
__device__ float g_ctx    [M_ * C_];            // 16 MB
__device__ float g_interT [67108864];           // 256 MB: (B,H,Tq,Tk)

// ---------------------------------------------------------------------------
// bf16 split-precision helpers: a = hi + lo captures ~16 mantissa bits.
// ---------------------------------------------------------------------------
__device__ __forceinline__ unsigned bf16pair(float x, float y) {
    __nv_bfloat162 t = __floats2bfloat162_rn(x, y);
    return reinterpret_cast<unsigned&>(t);
}
__device__ __forceinline__ float bf16hi(float x) {
    return __bfloat162float(__float2bfloat16(x));
}

__device__ __forceinline__ void mma16816(float* c, const unsigned* a,
                                         const unsigned* b) {
    asm volatile(
        "mma.sync.aligned.m16n8k16.row.col.f32.bf16.bf16.f32 "
        "{%0,%1,%2,%3}, {%4,%5,%6,%7}, {%8,%9}, {%0,%1,%2,%3};"
        : "+f"(c[0]), "+f"(c[1]), "+f"(c[2]), "+f"(c[3])
        : "r"(a[0]), "r"(a[1]), "r"(a[2]), "r"(a[3]),
          "r"(b[0]), "r"(b[1]));
}

// ---------------------------------------------------------------------------
// Tensor-core GEMM, bf16 2-term split (3 mma per product: hh + hl + lh).
// C[M,N] = A[M,K] @ B[K,N] (+bias). Block tile 128x128, BK=32, 256 threads,
// 8 warps in a 2(m) x 4(n) grid, warp tile 64x32 = 4x4 m16n8k16 mma tiles.
// smem:
//   A (hi/lo): word = bf16x2 over k-pair; layout [row][kpair], stride 20
//     -> fragment addr (20*g + tg) % 32 hits 32 distinct banks.
//   B (hi/lo): word = bf16x2 over k-pair; layout [kpair][n], stride 136
//     -> fragment addr (136*tg + g) % 32 = 8*tg+g, 32 distinct banks.
// Requires M%128==0, N%128==0, K%32==0 (true for all call sites).
// ---------------------------------------------------------------------------
__global__ __launch_bounds__(256, 2)
void hgemm_bf16x3(const float* __restrict__ A, const float* __restrict__ Bm,
                  float* __restrict__ Cm, int Mdim, int Ndim, int Kdim,
                  const float* __restrict__ bias)
{
    __shared__ unsigned Ahi[128 * 20];
    __shared__ unsigned Alo[128 * 20];
    __shared__ unsigned Bhi[16 * 136];
    __shared__ unsigned Blo[16 * 136];

    const int tid  = threadIdx.x;
    const int lane = tid & 31;
    const int wid  = tid >> 5;
    const int g    = lane >> 2;       // group id 0..7
    const int tg   = lane & 3;        // thread-in-group 0..3
    const int wm   = (wid & 1) * 64;  // warp m offset
    const int wn   = (wid >> 1) * 32; // warp n offset
    const int m0   = blockIdx.y * 128;
    const int n0   = blockIdx.x * 128;

    float acc[4][4][4];
#pragma unroll
    for (int i = 0; i < 4; i++)
#pragma unroll
        for (int j = 0; j < 4; j++)
#pragma unroll
            for (int t = 0; t < 4; t++) acc[i][j][t] = 0.f;

    for (int k0 = 0; k0 < Kdim; k0 += 32) {
        // ---- A tile: 128 rows x 32 k -> hi/lo bf16 pairs, [row][kpair] ----
#pragma unroll
        for (int i = 0; i < 4; i++) {
            int idx = tid + i * 256;
            int row = idx >> 3;
            int f4  = idx & 7;
            float4 a = *(const float4*)&A[(size_t)(m0 + row) * Kdim + k0 + f4 * 4];
            int w = row * 20 + f4 * 2;
            Ahi[w]     = bf16pair(a.x, a.y);
            Ahi[w + 1] = bf16pair(a.z, a.w);
            Alo[w]     = bf16pair(a.x - bf16hi(a.x), a.y - bf16hi(a.y));
            Alo[w + 1] = bf16pair(a.z - bf16hi(a.z), a.w - bf16hi(a.w));
        }
        // ---- B tile: 32 k x 128 n -> transposed to [kpair][n] bf16x2 ----
        {
            __nv_bfloat16* ph = reinterpret_cast<__nv_bfloat16*>(Bhi);
            __nv_bfloat16* pl = reinterpret_cast<__nv_bfloat16*>(Blo);
#pragma unroll
            for (int i = 0; i < 4; i++) {
                int idx = tid + i * 256;
                int kr  = idx >> 5;
                int n4  = (idx & 31) * 4;
                float4 b = *(const float4*)&Bm[(size_t)(k0 + kr) * Ndim + n0 + n4];
                int hb = ((kr >> 1) * 136) * 2 + (kr & 1);
                float vs[4] = {b.x, b.y, b.z, b.w};
#pragma unroll
                for (int j = 0; j < 4; j++) {
                    float v = vs[j];
                    __nv_bfloat16 h = __float2bfloat16(v);
                    ph[hb + (n4 + j) * 2] = h;
                    pl[hb + (n4 + j) * 2] = __float2bfloat16(v - __bfloat162float(h));
                }
            }
        }
        __syncthreads();

        // ---- compute: 2 k16 steps, 3-term split mma ----
#pragma unroll
        for (int s = 0; s < 2; s++) {
            const int pb = s * 8 + tg;
            unsigned bh[4][2], bl[4][2];
#pragma unroll
            for (int nt = 0; nt < 4; nt++) {
                int c = wn + nt * 8 + g;
                bh[nt][0] = Bhi[pb * 136 + c];
                bh[nt][1] = Bhi[(pb + 4) * 136 + c];
                bl[nt][0] = Blo[pb * 136 + c];
                bl[nt][1] = Blo[(pb + 4) * 136 + c];
            }
#pragma unroll
            for (int mt = 0; mt < 4; mt++) {
                int r = wm + mt * 16 + g;
                unsigned ah[4], al[4];
                ah[0] = Ahi[r * 20 + pb];
                ah[1] = Ahi[(r + 8) * 20 + pb];
                ah[2] = Ahi[r * 20 + pb + 4];
                ah[3] = Ahi[(r + 8) * 20 + pb + 4];
                al[0] = Alo[r * 20 + pb];
                al[1] = Alo[(r + 8) * 20 + pb];
                al[2] = Alo[r * 20 + pb + 4];
                al[3] = Alo[(r + 8) * 20 + pb + 4];
#pragma unroll
                for (int nt = 0; nt < 4; nt++) {
                    mma16816(acc[mt][nt], ah, bh[nt]);  // hi*hi
                    mma16816(acc[mt][nt], ah, bl[nt]);  // hi*lo
                    mma16816(acc[mt][nt], al, bh[nt]);  // lo*hi
                }
            }
        }
        __syncthreads();
    }

    // ---- epilogue ----
#pragma unroll
    for (int mt = 0; mt < 4; mt++) {
        int r = m0 + wm + mt * 16 + g;
#pragma unroll
        for (int nt = 0; nt < 4; nt++) {
            int c = n0 + wn + nt * 8 + tg * 2;
            float b0 = 0.f, b1 = 0.f;
            if (bias) { b0 = bias[c]; b1 = bias[c + 1]; }
            float2 v0 = make_float2(acc[mt][nt][0] + b0, acc[mt][nt][1] + b1);
            float2 v1 = make_float2(acc[mt][nt][2] + b0, acc[mt][nt][3] + b1);
            *(float2*)&Cm[(size_t)r * Ndim + c]       = v0;
            *(float2*)&Cm[(size_t)(r + 8) * Ndim + c] = v1;
        }
    }
}

// ---------------------------------------------------------------------------
// interaction_matrix transpose: (B, Tk, Tq, H) -> (B, H, Tq, Tk).
// Tile = (k:16, q:16, h:16). Source reads are 256-float contiguous runs
// (q*H+h contiguous); dest writes are 16-float (64B) aligned runs in k.
// ---------------------------------------------------------------------------
__global__ __launch_bounds__(256)
void transpose_inter(const float* __restrict__ src, float* __restrict__ dst)
{
    __shared__ float s[16][256];
    const int t  = threadIdx.x;
    const int k0 = blockIdx.x * 16;
    const int q0 = blockIdx.y * 16;
    const int b  = blockIdx.z;

    const float* sp = src + (size_t)b * T_ * T_ * H_ + (size_t)q0 * H_;
#pragma unroll
    for (int kk = 0; kk < 16; kk++)
        s[kk][t] = sp[(size_t)(k0 + kk) * T_ * H_ + t];
    __syncthreads();

    const int q = t >> 4;
    const int h = t & 15;
    float* dp = dst + ((size_t)(b * H_ + h) * T_ + q0 + q) * T_ + k0;
#pragma unroll
    for (int kk4 = 0; kk4 < 4; kk4++) {
        float4 v = make_float4(s[kk4 * 4 + 0][t], s[kk4 * 4 + 1][t],
                               s[kk4 * 4 + 2][t], s[kk4 * 4 + 3][t]);
        *(float4*)&dp[kk4 * 4] = v;
    }
}

// ---------------------------------------------------------------------------
// Flash attention with interaction bias + padding + causal masks (fp32).
// Block: 256 threads = 64 q-rows x 4 lanes/row. Br=64, Bc=32, D=64.
// Unchanged from round 6 (validated, rel_err 7.3e-07).
// ---------------------------------------------------------------------------
__global__ __launch_bounds__(256)
void attn_kernel(const float* __restrict__ Q, const float* __restrict__ K,
                 const float* __restrict__ V, const int* __restrict__ pad,
                 const float* __restrict__ interT, float* __restrict__ ctx)
{
    __shared__ float q_s[64 * 68];
    __shared__ float k_s[32 * 68];
    __shared__ float v_s[32 * 68];
    __shared__ float p_s[64 * 36];   // holds interaction tile, then P tile

    const float NEG_INF = __int_as_float(0xff800000);

    const int tid = threadIdx.x;
    const int r   = tid >> 2;        // q-row within tile (0..63)
    const int c4  = tid & 3;         // lane within row (0..3)
    const int q0  = blockIdx.x * 64;
    const int h   = blockIdx.y;
    const int b   = blockIdx.z;

    const float* qp = Q + (size_t)(b * T_) * C_ + h * D_;
    const float* kp = K + (size_t)(b * T_) * C_ + h * D_;
    const float* vp = V + (size_t)(b * T_) * C_ + h * D_;
    const float* ip = interT + ((size_t)(b * H_ + h) * T_) * T_;

    // Load Q tile (64 x 64): 1024 float4
#pragma unroll
    for (int it = 0; it < 4; it++) {
        int idx = tid + it * 256;
        int row = idx >> 4, d4 = (idx & 15) * 4;
        *(float4*)&q_s[row * 68 + d4] =
            *(const float4*)&qp[(size_t)(q0 + row) * C_ + d4];
    }

    const int myq = q0 + r;
    const int pd  = pad[b * T_ + myq];

    float m = NEG_INF, l = 0.f;
    float4 acc0 = {0,0,0,0}, acc1 = {0,0,0,0}, acc2 = {0,0,0,0}, acc3 = {0,0,0,0};

    for (int k0 = 0; k0 < q0 + 64; k0 += 32) {
        // Cooperative loads: K tile, V tile (32x64), interaction tile (64x32)
#pragma unroll
        for (int it = 0; it < 2; it++) {
            int idx = tid + it * 256;
            int row = idx >> 4, d4 = (idx & 15) * 4;
            *(float4*)&k_s[row * 68 + d4] =
                *(const float4*)&kp[(size_t)(k0 + row) * C_ + d4];
            *(float4*)&v_s[row * 68 + d4] =
                *(const float4*)&vp[(size_t)(k0 + row) * C_ + d4];
            int irow = idx >> 3, ic = (idx & 7) * 4;
            *(float4*)&p_s[irow * 36 + ic] =
                *(const float4*)&ip[(size_t)(q0 + irow) * T_ + k0 + ic];
        }
        __syncthreads();

        // S = 0.125 * Q K^T  (8 columns per thread, c = c4 + 4j)
        float s[8];
#pragma unroll
        for (int j = 0; j < 8; j++) s[j] = 0.f;
#pragma unroll
        for (int d = 0; d < 64; d += 4) {
            float4 qv = *(float4*)&q_s[r * 68 + d];
#pragma unroll
            for (int j = 0; j < 8; j++) {
                int c = c4 + 4 * j;
                float4 kv = *(float4*)&k_s[c * 68 + d];
                s[j] += qv.x * kv.x + qv.y * kv.y + qv.z * kv.z + qv.w * kv.w;
            }
        }

        // masks + interaction bias, tile row-max
        float mt = NEG_INF;
#pragma unroll
        for (int j = 0; j < 8; j++) {
            int c = c4 + 4 * j;
            float sv = s[j] * 0.125f;
            if (pd == 0)          sv = -1e9f;
            if (k0 + c > myq)     sv = NEG_INF;
            sv += p_s[r * 36 + c];           // interaction (finite; -inf stays)
            s[j] = sv;
            mt = fmaxf(mt, sv);
        }
        mt = fmaxf(mt, __shfl_xor_sync(0xffffffffu, mt, 1));
        mt = fmaxf(mt, __shfl_xor_sync(0xffffffffu, mt, 2));

        float mnew = fmaxf(m, mt);
        float f = (m == NEG_INF) ? 0.f : __expf(m - mnew);

        float lt = 0.f;
#pragma unroll
        for (int j = 0; j < 8; j++) {
            float p = (s[j] == NEG_INF) ? 0.f : __expf(s[j] - mnew);
            s[j] = p;
            lt += p;
        }
        lt += __shfl_xor_sync(0xffffffffu, lt, 1);
        lt += __shfl_xor_sync(0xffffffffu, lt, 2);
        l = l * f + lt;
        m = mnew;

        acc0.x *= f; acc0.y *= f; acc0.z *= f; acc0.w *= f;
        acc1.x *= f; acc1.y *= f; acc1.z *= f; acc1.w *= f;
        acc2.x *= f; acc2.y *= f; acc2.z *= f; acc2.w *= f;
        acc3.x *= f; acc3.y *= f; acc3.z *= f; acc3.w *= f;

        // publish P tile (each thread writes exactly the slots it read)
#pragma unroll
        for (int j = 0; j < 8; j++) p_s[r * 36 + c4 + 4 * j] = s[j];
        __syncthreads();

        // ctx += P V : thread owns d = 4*c4 + 16*i (+0..3), i = 0..3
        const int dof = c4 * 4;
#pragma unroll 8
        for (int c = 0; c < 32; c++) {
            float pv = p_s[r * 36 + c];
            float4 v0 = *(float4*)&v_s[c * 68 + dof];
            float4 v1 = *(float4*)&v_s[c * 68 + 16 + dof];
            float4 v2 = *(float4*)&v_s[c * 68 + 32 + dof];
            float4 v3 = *(float4*)&v_s[c * 68 + 48 + dof];
            acc0.x += pv * v0.x; acc0.y += pv * v0.y; acc0.z += pv * v0.z; acc0.w += pv * v0.w;
            acc1.x += pv * v1.x; acc1.y += pv * v1.y; acc1.z += pv * v1.z; acc1.w += pv * v1.w;
            acc2.x += pv * v2.x; acc2.y += pv * v2.y; acc2.z += pv * v2.z; acc2.w += pv * v2.w;
            acc3.x += pv * v3.x; acc3.y += pv * v3.y; acc3.z += pv * v3.z; acc3.w += pv * v3.w;
        }
        __syncthreads();   // protect k_s/v_s/p_s before next tile's loads
    }

    // epilogue: normalize and write ctx in (B,T,C) layout
    const float inv = 1.f / l;
    float* op = ctx + (size_t)(b * T_ + myq) * C_ + h * D_ + c4 * 4;
    float4 o;
    o = make_float4(acc0.x * inv, acc0.y * inv, acc0.z * inv, acc0.w * inv); *(float4*)&op[0]  = o;
    o = make_float4(acc1.x * inv, acc1.y * inv, acc1.z * inv, acc1.w * inv); *(float4*)&op[16] = o;
    o = make_float4(acc2.x * inv, acc2.y * inv, acc2.z * inv, acc2.w * inv); *(float4*)&op[32] = o;
    o = make_float4(acc3.x * inv, acc3.y * inv, acc3.z * inv, acc3.w * inv); *(float4*)&op[48] = o;
}

// ---------------------------------------------------------------------------
// Launch: 5 projection GEMMs (tensor-core), interaction transpose, attention,
// output GEMM. Default stream -> sequential dependencies, graph-capturable.
// ---------------------------------------------------------------------------
extern "C" void kernel_launch(void* const* d_in, const int* in_sizes, int n_in,
                              void* d_out, int out_size)
{
    const float* x       = (const float*)d_in[0];
    const int*   padding = (const int*)  d_in[1];
    const float* inter   = (const float*)d_in[2];
    const float* W_ckv   = (const float*)d_in[3];
    const float* W_cq    = (const float*)d_in[4];
    const float* W_kc    = (const float*)d_in[5];
    const float* W_qc    = (const float*)d_in[6];
    const float* W_vc    = (const float*)d_in[7];
    const float* W_proj  = (const float*)d_in[8];
    const float* b_proj  = (const float*)d_in[9];
    float* out = (float*)d_out;

    float *kv_down, *q_down, *kb, *qb, *vb, *ctx, *interT;
    cudaGetSymbolAddress((void**)&kv_down, g_kv_down);
    cudaGetSymbolAddress((void**)&q_down,  g_q_down);
    cudaGetSymbolAddress((void**)&kb,      g_k);
    cudaGetSymbolAddress((void**)&qb,      g_q);
    cudaGetSymbolAddress((void**)&vb,      g_v);
    cudaGetSymbolAddress((void**)&ctx,     g_ctx);
    cudaGetSymbolAddress((void**)&interT,  g_interT);

    dim3 blk(256);

    // down projections: (4096x1024)@(1024x256)
    hgemm_bf16x3<<<dim3(L_ / 128, M_ / 128), blk>>>(x, W_ckv, kv_down, M_, L_, C_, nullptr);
    hgemm_bf16x3<<<dim3(L_ / 128, M_ / 128), blk>>>(x, W_cq,  q_down,  M_, L_, C_, nullptr);

    // up projections: (4096x256)@(256x1024), (B,T,C) layout == (B,T,H,D)
    hgemm_bf16x3<<<dim3(C_ / 128, M_ / 128), blk>>>(kv_down, W_kc, kb, M_, C_, L_, nullptr);
    hgemm_bf16x3<<<dim3(C_ / 128, M_ / 128), blk>>>(q_down,  W_qc, qb, M_, C_, L_, nullptr);
    hgemm_bf16x3<<<dim3(C_ / 128, M_ / 128), blk>>>(kv_down, W_vc, vb, M_, C_, L_, nullptr);

    // interaction matrix (B,Tk,Tq,H) -> (B,H,Tq,Tk)
    transpose_inter<<<dim3(T_ / 16, T_ / 16, B_), blk>>>(inter, interT);

    // attention -> ctx (B,T,C)
    attn_kernel<<<dim3(T_ / 64, H_, B_), blk>>>(qb, kb, vb, padding, interT, ctx);

    // output projection: (4096x1024)@(1024x1024) + bias
    hgemm_bf16x3<<<dim3(C_ / 128, M_ / 128), blk>>>(ctx, W_proj, out, M_, C_, C_, b_proj);
}

// round 10
// speedup vs baseline: 2.4018x; 1.8328x over previous
#include <cuda_runtime.h>
#include <cuda_bf16.h>

// Problem constants
#define B_ 4
#define T_ 1024
#define C_ 1024
#define H_ 16
#define L_ 256
#define D_ 64
#define M_ (B_*T_)   // 4096 rows

// ---------------------------------------------------------------------------
// Scratch (device globals: no allocation allowed in kernel_launch)
// ---------------------------------------------------------------------------
__device__ float g_kv_down[M_ * L_];            //  4 MB
__device__ float g_q_down [M_ * L_];            //  4 MB
__device__ float g_k      [M_ * C_];            // 16 MB  (B,T,C) row-major
__device__ float g_q      [M_ * C_];            // 16 MB
__device__ float g_v      [M_ * C_];            // 16 MB
__device__ float g_ctx    [M_ * C_];            // 16 MB
__device__ float g_interT [67108864];           // 256 MB: (B,H,Tq,Tk)

// ---------------------------------------------------------------------------
// bf16 split-precision helpers: a = hi + lo captures ~16 mantissa bits.
// ---------------------------------------------------------------------------
__device__ __forceinline__ unsigned bf16pair(float x, float y) {
    __nv_bfloat162 t = __floats2bfloat162_rn(x, y);
    return reinterpret_cast<unsigned&>(t);
}
__device__ __forceinline__ float bf16hi(float x) {
    return __bfloat162float(__float2bfloat16(x));
}
__device__ __forceinline__ void split2(unsigned& hi, unsigned& lo,
                                       float x, float y) {
    float hx = bf16hi(x), hy = bf16hi(y);
    hi = bf16pair(x, y);
    lo = bf16pair(x - hx, y - hy);
}

__device__ __forceinline__ void mma16816(float* c, const unsigned* a,
                                         const unsigned* b) {
    asm volatile(
        "mma.sync.aligned.m16n8k16.row.col.f32.bf16.bf16.f32 "
        "{%0,%1,%2,%3}, {%4,%5,%6,%7}, {%8,%9}, {%0,%1,%2,%3};"
        : "+f"(c[0]), "+f"(c[1]), "+f"(c[2]), "+f"(c[3])
        : "r"(a[0]), "r"(a[1]), "r"(a[2]), "r"(a[3]),
          "r"(b[0]), "r"(b[1]));
}

// ---------------------------------------------------------------------------
// Tensor-core GEMM, bf16 2-term split (3 mma per product: hh + hl + lh).
// C[M,N] = A[M,K] @ B[K,N] (+bias). Block tile 128x128, BK=32, 256 threads,
// 8 warps in a 2(m) x 4(n) grid, warp tile 64x32 = 4x4 m16n8k16 mma tiles.
// Validated round 7/8 (rel_err 7.6e-6, 32.2us for 4096x1024x256).
// ---------------------------------------------------------------------------
__global__ __launch_bounds__(256, 2)
void hgemm_bf16x3(const float* __restrict__ A, const float* __restrict__ Bm,
                  float* __restrict__ Cm, int Mdim, int Ndim, int Kdim,
                  const float* __restrict__ bias)
{
    __shared__ unsigned Ahi[128 * 20];
    __shared__ unsigned Alo[128 * 20];
    __shared__ unsigned Bhi[16 * 136];
    __shared__ unsigned Blo[16 * 136];

    const int tid  = threadIdx.x;
    const int lane = tid & 31;
    const int wid  = tid >> 5;
    const int g    = lane >> 2;
    const int tg   = lane & 3;
    const int wm   = (wid & 1) * 64;
    const int wn   = (wid >> 1) * 32;
    const int m0   = blockIdx.y * 128;
    const int n0   = blockIdx.x * 128;

    float acc[4][4][4];
#pragma unroll
    for (int i = 0; i < 4; i++)
#pragma unroll
        for (int j = 0; j < 4; j++)
#pragma unroll
            for (int t = 0; t < 4; t++) acc[i][j][t] = 0.f;

    for (int k0 = 0; k0 < Kdim; k0 += 32) {
#pragma unroll
        for (int i = 0; i < 4; i++) {
            int idx = tid + i * 256;
            int row = idx >> 3;
            int f4  = idx & 7;
            float4 a = *(const float4*)&A[(size_t)(m0 + row) * Kdim + k0 + f4 * 4];
            int w = row * 20 + f4 * 2;
            Ahi[w]     = bf16pair(a.x, a.y);
            Ahi[w + 1] = bf16pair(a.z, a.w);
            Alo[w]     = bf16pair(a.x - bf16hi(a.x), a.y - bf16hi(a.y));
            Alo[w + 1] = bf16pair(a.z - bf16hi(a.z), a.w - bf16hi(a.w));
        }
        {
            __nv_bfloat16* ph = reinterpret_cast<__nv_bfloat16*>(Bhi);
            __nv_bfloat16* pl = reinterpret_cast<__nv_bfloat16*>(Blo);
#pragma unroll
            for (int i = 0; i < 4; i++) {
                int idx = tid + i * 256;
                int kr  = idx >> 5;
                int n4  = (idx & 31) * 4;
                float4 b = *(const float4*)&Bm[(size_t)(k0 + kr) * Ndim + n0 + n4];
                int hb = ((kr >> 1) * 136) * 2 + (kr & 1);
                float vs[4] = {b.x, b.y, b.z, b.w};
#pragma unroll
                for (int j = 0; j < 4; j++) {
                    float v = vs[j];
                    __nv_bfloat16 h = __float2bfloat16(v);
                    ph[hb + (n4 + j) * 2] = h;
                    pl[hb + (n4 + j) * 2] = __float2bfloat16(v - __bfloat162float(h));
                }
            }
        }
        __syncthreads();

#pragma unroll
        for (int s = 0; s < 2; s++) {
            const int pb = s * 8 + tg;
            unsigned bh[4][2], bl[4][2];
#pragma unroll
            for (int nt = 0; nt < 4; nt++) {
                int c = wn + nt * 8 + g;
                bh[nt][0] = Bhi[pb * 136 + c];
                bh[nt][1] = Bhi[(pb + 4) * 136 + c];
                bl[nt][0] = Blo[pb * 136 + c];
                bl[nt][1] = Blo[(pb + 4) * 136 + c];
            }
#pragma unroll
            for (int mt = 0; mt < 4; mt++) {
                int r = wm + mt * 16 + g;
                unsigned ah[4], al[4];
                ah[0] = Ahi[r * 20 + pb];
                ah[1] = Ahi[(r + 8) * 20 + pb];
                ah[2] = Ahi[r * 20 + pb + 4];
                ah[3] = Ahi[(r + 8) * 20 + pb + 4];
                al[0] = Alo[r * 20 + pb];
                al[1] = Alo[(r + 8) * 20 + pb];
                al[2] = Alo[r * 20 + pb + 4];
                al[3] = Alo[(r + 8) * 20 + pb + 4];
#pragma unroll
                for (int nt = 0; nt < 4; nt++) {
                    mma16816(acc[mt][nt], ah, bh[nt]);
                    mma16816(acc[mt][nt], ah, bl[nt]);
                    mma16816(acc[mt][nt], al, bh[nt]);
                }
            }
        }
        __syncthreads();
    }

#pragma unroll
    for (int mt = 0; mt < 4; mt++) {
        int r = m0 + wm + mt * 16 + g;
#pragma unroll
        for (int nt = 0; nt < 4; nt++) {
            int c = n0 + wn + nt * 8 + tg * 2;
            float b0 = 0.f, b1 = 0.f;
            if (bias) { b0 = bias[c]; b1 = bias[c + 1]; }
            float2 v0 = make_float2(acc[mt][nt][0] + b0, acc[mt][nt][1] + b1);
            float2 v1 = make_float2(acc[mt][nt][2] + b0, acc[mt][nt][3] + b1);
            *(float2*)&Cm[(size_t)r * Ndim + c]       = v0;
            *(float2*)&Cm[(size_t)(r + 8) * Ndim + c] = v1;
        }
    }
}

// ---------------------------------------------------------------------------
// interaction_matrix transpose v2: (B, Tk, Tq, H) -> (B, H, Tq, Tk).
// Tile (k:32, q:8, h:16). Reads: per k-row 128B-contiguous runs (coalesced).
// Writes: warp writes 32 consecutive k floats per (h,q) row = 128B coalesced.
// smem [k][qh] stride 129: conflict-free both phases.
// ---------------------------------------------------------------------------
__global__ __launch_bounds__(256)
void transpose_inter2(const float* __restrict__ src, float* __restrict__ dst)
{
    __shared__ float s[32 * 129];
    const int t    = threadIdx.x;
    const int lane = t & 31;
    const int w    = t >> 5;
    const int k0   = blockIdx.x * 32;
    const int q0   = blockIdx.y * 8;
    const int b    = blockIdx.z;

    const int k  = t >> 3;            // 0..31
    const int f4b = t & 7;
    const float* sp = src + (size_t)(b * T_ + k0 + k) * (T_ * H_) + q0 * H_;
#pragma unroll
    for (int p = 0; p < 4; p++) {
        int f4 = f4b + p * 8;         // 0..31
        float4 v = *(const float4*)&sp[f4 * 4];
        s[k * 129 + f4 * 4 + 0] = v.x;
        s[k * 129 + f4 * 4 + 1] = v.y;
        s[k * 129 + f4 * 4 + 2] = v.z;
        s[k * 129 + f4 * 4 + 3] = v.w;
    }
    __syncthreads();

#pragma unroll
    for (int r = 0; r < 16; r++) {
        int qh = w * 16 + r;          // 0..127
        int q  = qh >> 4;
        int h  = qh & 15;
        float v = s[lane * 129 + qh];
        dst[((size_t)(b * H_ + h) * T_ + q0 + q) * T_ + k0 + lane] = v;
    }
}

// ---------------------------------------------------------------------------
// Tensor-core flash attention, bf16 2-term split (3 mma), FA2-style.
// Grid (T/64, H, B), 128 threads = 4 warps. Each warp owns 16 q-rows
// (rows w*16+g, +8) across the FULL 64-col key tile -> softmax reductions are
// intra-warp shfl only. Q (pre-scaled by 0.125) lives in registers as mma
// A-fragments; S accum fragment == P A-fragment (no smem round-trip for P).
// K smem [key][dpair] stride 36, V smem [keypair][d] stride 72: conflict-free.
// Interaction bias read per-thread as float2 from transposed layout.
// ---------------------------------------------------------------------------
__global__ __launch_bounds__(128)
void attn_mma(const float* __restrict__ Q, const float* __restrict__ K,
              const float* __restrict__ V, const int* __restrict__ pad,
              const float* __restrict__ interT, float* __restrict__ ctx)
{
    __shared__ unsigned Khi[64 * 36], Klo[64 * 36];
    __shared__ unsigned Vhi[32 * 72], Vlo[32 * 72];

    const float NEG = __int_as_float(0xff800000);   // -inf

    const int tid  = threadIdx.x;
    const int lane = tid & 31;
    const int w    = tid >> 5;        // warp 0..3
    const int g    = lane >> 2;       // 0..7
    const int tg   = lane & 3;        // 0..3
    const int q0   = blockIdx.x * 64;
    const int h    = blockIdx.y;
    const int b    = blockIdx.z;

    const int row0 = q0 + w * 16 + g;     // q row for accum c0,c1
    const int row1 = row0 + 8;            // q row for accum c2,c3

    // ---- Q fragments in registers (scaled by 0.125 = exact) ----
    unsigned ah[4][4], al[4][4];
#pragma unroll
    for (int rsel = 0; rsel < 2; rsel++) {
        int row = rsel ? row1 : row0;
        const float* qp = Q + (size_t)(b * T_ + row) * C_ + h * D_ + 2 * tg;
#pragma unroll
        for (int m = 0; m < 8; m++) {
            float2 v = *(const float2*)&qp[m * 8];
            v.x *= 0.125f; v.y *= 0.125f;
            int s   = m >> 1;
            int idx = ((m & 1) << 1) | rsel;
            split2(ah[s][idx], al[s][idx], v.x, v.y);
        }
    }

    const int pd0 = pad[b * T_ + row0];
    const int pd1 = pad[b * T_ + row1];
    const float* ip0 = interT + ((size_t)(b * H_ + h) * T_ + row0) * T_ + 2 * tg;
    const float* ip1 = interT + ((size_t)(b * H_ + h) * T_ + row1) * T_ + 2 * tg;

    float m0 = NEG, m1 = NEG, l0 = 0.f, l1 = 0.f;
    float o[8][4];
#pragma unroll
    for (int j = 0; j < 8; j++)
#pragma unroll
        for (int i = 0; i < 4; i++) o[j][i] = 0.f;

    const float* kbase = K + (size_t)(b * T_) * C_ + h * D_;
    const float* vbase = V + (size_t)(b * T_) * C_ + h * D_;

    for (int k0 = 0; k0 < q0 + 64; k0 += 64) {
        __syncthreads();   // smem consumed by previous iteration's mma
        // ---- K tile: 64 keys x 64 d -> hi/lo pairs [key][dpair] ----
#pragma unroll
        for (int i = 0; i < 8; i++) {
            int idx = tid + i * 128;
            int kr  = idx >> 4;
            int d4  = (idx & 15) * 4;
            float4 kv = *(const float4*)&kbase[(size_t)(k0 + kr) * C_ + d4];
            int wb = kr * 36 + d4 / 2;
            unsigned h0, l0w, h1, l1w;
            split2(h0, l0w, kv.x, kv.y);
            split2(h1, l1w, kv.z, kv.w);
            Khi[wb] = h0; Khi[wb + 1] = h1;
            Klo[wb] = l0w; Klo[wb + 1] = l1w;
        }
        // ---- V tile: 64 keys x 64 d -> key-pair packed [kp][d] ----
        {
            __nv_bfloat16* vh = reinterpret_cast<__nv_bfloat16*>(Vhi);
            __nv_bfloat16* vl = reinterpret_cast<__nv_bfloat16*>(Vlo);
#pragma unroll
            for (int i = 0; i < 8; i++) {
                int idx = tid + i * 128;
                int vr  = idx >> 4;
                int d4  = (idx & 15) * 4;
                float4 vv = *(const float4*)&vbase[(size_t)(k0 + vr) * C_ + d4];
                int half = vr & 1;
                int wb   = (vr >> 1) * 72 + d4;
                float vs[4] = {vv.x, vv.y, vv.z, vv.w};
#pragma unroll
                for (int j = 0; j < 4; j++) {
                    __nv_bfloat16 hv = __float2bfloat16(vs[j]);
                    vh[(wb + j) * 2 + half] = hv;
                    vl[(wb + j) * 2 + half] =
                        __float2bfloat16(vs[j] - __bfloat162float(hv));
                }
            }
        }
        __syncthreads();

        // ---- bias loads (independent of mma; compiler overlaps) ----
        float2 bias0[8], bias1[8];
#pragma unroll
        for (int j = 0; j < 8; j++) {
            bias0[j] = *(const float2*)&ip0[k0 + 8 * j];
            bias1[j] = *(const float2*)&ip1[k0 + 8 * j];
        }

        // ---- S = (0.125*Q) K^T via split mma ----
        float sc[8][4];
#pragma unroll
        for (int j = 0; j < 8; j++)
#pragma unroll
            for (int i = 0; i < 4; i++) sc[j][i] = 0.f;
#pragma unroll
        for (int j = 0; j < 8; j++) {
            const int c = (8 * j + g) * 36;
#pragma unroll
            for (int s = 0; s < 2; s++) {
#pragma unroll
                for (int ss = 0; ss < 2; ss++) {
                    int st = s * 2 + ss;
                    unsigned bh[2] = {Khi[c + st * 8 + tg], Khi[c + st * 8 + tg + 4]};
                    unsigned bl[2] = {Klo[c + st * 8 + tg], Klo[c + st * 8 + tg + 4]};
                    mma16816(sc[j], ah[st], bh);
                    mma16816(sc[j], ah[st], bl);
                    mma16816(sc[j], al[st], bh);
                }
            }
        }

        // ---- masks + bias + online softmax ----
        float mt0 = NEG, mt1 = NEG;
#pragma unroll
        for (int j = 0; j < 8; j++) {
            int kc = k0 + 8 * j + 2 * tg;
            float v0 = sc[j][0], v1 = sc[j][1], v2 = sc[j][2], v3 = sc[j][3];
            if (pd0 == 0) { v0 = -1e9f; v1 = -1e9f; }
            if (pd1 == 0) { v2 = -1e9f; v3 = -1e9f; }
            if (kc     > row0) v0 = NEG;
            if (kc + 1 > row0) v1 = NEG;
            if (kc     > row1) v2 = NEG;
            if (kc + 1 > row1) v3 = NEG;
            v0 += bias0[j].x; v1 += bias0[j].y;
            v2 += bias1[j].x; v3 += bias1[j].y;
            sc[j][0] = v0; sc[j][1] = v1; sc[j][2] = v2; sc[j][3] = v3;
            mt0 = fmaxf(mt0, fmaxf(v0, v1));
            mt1 = fmaxf(mt1, fmaxf(v2, v3));
        }
        mt0 = fmaxf(mt0, __shfl_xor_sync(0xffffffffu, mt0, 1));
        mt0 = fmaxf(mt0, __shfl_xor_sync(0xffffffffu, mt0, 2));
        mt1 = fmaxf(mt1, __shfl_xor_sync(0xffffffffu, mt1, 1));
        mt1 = fmaxf(mt1, __shfl_xor_sync(0xffffffffu, mt1, 2));

        float mn0 = fmaxf(m0, mt0), mn1 = fmaxf(m1, mt1);
        float f0 = __expf(m0 - mn0);   // m0=-inf first tile -> 0
        float f1 = __expf(m1 - mn1);

        float lt0 = 0.f, lt1 = 0.f;
#pragma unroll
        for (int j = 0; j < 8; j++) {
            float p0 = __expf(sc[j][0] - mn0);   // -inf -> 0 (mn finite)
            float p1 = __expf(sc[j][1] - mn0);
            float p2 = __expf(sc[j][2] - mn1);
            float p3 = __expf(sc[j][3] - mn1);
            sc[j][0] = p0; sc[j][1] = p1; sc[j][2] = p2; sc[j][3] = p3;
            lt0 += p0 + p1; lt1 += p2 + p3;
        }
        lt0 += __shfl_xor_sync(0xffffffffu, lt0, 1);
        lt0 += __shfl_xor_sync(0xffffffffu, lt0, 2);
        lt1 += __shfl_xor_sync(0xffffffffu, lt1, 1);
        lt1 += __shfl_xor_sync(0xffffffffu, lt1, 2);
        l0 = l0 * f0 + lt0; m0 = mn0;
        l1 = l1 * f1 + lt1; m1 = mn1;

#pragma unroll
        for (int j = 0; j < 8; j++) {
            o[j][0] *= f0; o[j][1] *= f0;
            o[j][2] *= f1; o[j][3] *= f1;
        }

        // ---- P fragments: S accum layout == A-frag layout ----
        unsigned ph[4][4], pl[4][4];
#pragma unroll
        for (int s = 0; s < 4; s++) {
            split2(ph[s][0], pl[s][0], sc[2 * s][0],     sc[2 * s][1]);
            split2(ph[s][1], pl[s][1], sc[2 * s][2],     sc[2 * s][3]);
            split2(ph[s][2], pl[s][2], sc[2 * s + 1][0], sc[2 * s + 1][1]);
            split2(ph[s][3], pl[s][3], sc[2 * s + 1][2], sc[2 * s + 1][3]);
        }

        // ---- O += P V via split mma ----
#pragma unroll
        for (int j = 0; j < 8; j++) {
            const int c = 8 * j + g;
#pragma unroll
            for (int s = 0; s < 4; s++) {
                unsigned bh[2] = {Vhi[(s * 8 + tg) * 72 + c],
                                  Vhi[(s * 8 + tg + 4) * 72 + c]};
                unsigned bl[2] = {Vlo[(s * 8 + tg) * 72 + c],
                                  Vlo[(s * 8 + tg + 4) * 72 + c]};
                mma16816(o[j], ph[s], bh);
                mma16816(o[j], ph[s], bl);
                mma16816(o[j], pl[s], bh);
            }
        }
    }

    // ---- epilogue: normalize, write ctx (B,T,C) ----
    const float inv0 = 1.f / l0, inv1 = 1.f / l1;
    float* op0 = ctx + (size_t)(b * T_ + row0) * C_ + h * D_ + 2 * tg;
    float* op1 = ctx + (size_t)(b * T_ + row1) * C_ + h * D_ + 2 * tg;
#pragma unroll
    for (int j = 0; j < 8; j++) {
        *(float2*)&op0[8 * j] = make_float2(o[j][0] * inv0, o[j][1] * inv0);
        *(float2*)&op1[8 * j] = make_float2(o[j][2] * inv1, o[j][3] * inv1);
    }
}

// ---------------------------------------------------------------------------
// Launch: 5 projection GEMMs (tensor-core), transpose, mma attention, output
// GEMM. Default stream -> sequential dependencies, graph-capturable.
// ---------------------------------------------------------------------------
extern "C" void kernel_launch(void* const* d_in, const int* in_sizes, int n_in,
                              void* d_out, int out_size)
{
    const float* x       = (const float*)d_in[0];
    const int*   padding = (const int*)  d_in[1];
    const float* inter   = (const float*)d_in[2];
    const float* W_ckv   = (const float*)d_in[3];
    const float* W_cq    = (const float*)d_in[4];
    const float* W_kc    = (const float*)d_in[5];
    const float* W_qc    = (const float*)d_in[6];
    const float* W_vc    = (const float*)d_in[7];
    const float* W_proj  = (const float*)d_in[8];
    const float* b_proj  = (const float*)d_in[9];
    float* out = (float*)d_out;

    float *kv_down, *q_down, *kb, *qb, *vb, *ctx, *interT;
    cudaGetSymbolAddress((void**)&kv_down, g_kv_down);
    cudaGetSymbolAddress((void**)&q_down,  g_q_down);
    cudaGetSymbolAddress((void**)&kb,      g_k);
    cudaGetSymbolAddress((void**)&qb,      g_q);
    cudaGetSymbolAddress((void**)&vb,      g_v);
    cudaGetSymbolAddress((void**)&ctx,     g_ctx);
    cudaGetSymbolAddress((void**)&interT,  g_interT);

    dim3 blk(256);

    // down projections: (4096x1024)@(1024x256)
    hgemm_bf16x3<<<dim3(L_ / 128, M_ / 128), blk>>>(x, W_ckv, kv_down, M_, L_, C_, nullptr);
    hgemm_bf16x3<<<dim3(L_ / 128, M_ / 128), blk>>>(x, W_cq,  q_down,  M_, L_, C_, nullptr);

    // up projections: (4096x256)@(256x1024), (B,T,C) layout == (B,T,H,D)
    hgemm_bf16x3<<<dim3(C_ / 128, M_ / 128), blk>>>(kv_down, W_kc, kb, M_, C_, L_, nullptr);
    hgemm_bf16x3<<<dim3(C_ / 128, M_ / 128), blk>>>(q_down,  W_qc, qb, M_, C_, L_, nullptr);
    hgemm_bf16x3<<<dim3(C_ / 128, M_ / 128), blk>>>(kv_down, W_vc, vb, M_, C_, L_, nullptr);

    // interaction matrix (B,Tk,Tq,H) -> (B,H,Tq,Tk)
    transpose_inter2<<<dim3(T_ / 32, T_ / 8, B_), blk>>>(inter, interT);

    // attention -> ctx (B,T,C)
    attn_mma<<<dim3(T_ / 64, H_, B_), dim3(128)>>>(qb, kb, vb, padding, interT, ctx);

    // output projection: (4096x1024)@(1024x1024) + bias
    hgemm_bf16x3<<<dim3(C_ / 128, M_ / 128), blk>>>(ctx, W_proj, out, M_, C_, C_, b_proj);
}